// round 2
// baseline (speedup 1.0000x reference)
#include <cuda_runtime.h>

// Problem constants
#define Bsz 8192
#define Din 1024
#define Rk  64
#define RS  4096

// Scratch (no cudaMalloc allowed) — ~71MB of __device__ globals.
__device__ float g_u[Bsz * Rk];
__device__ float g_h[Bsz * Rk];
__device__ float g_act0[Bsz * Din];
__device__ float g_act1[Bsz * Din];

// Select activation source/dest without needing cudaGetSymbolAddress on host.
__device__ __forceinline__ const float* in_sel(const float* ext, int sel) {
    if (sel == 0) return g_act0;
    if (sel == 1) return g_act1;
    return ext;
}
__device__ __forceinline__ float* out_sel(float* ext, int sel) {
    if (sel == 0) return g_act0;
    if (sel == 1) return g_act1;
    return ext;
}

// ---- packed fp32x2 helpers (sm_100+; ptxas never auto-emits FFMA2) ----
__device__ __forceinline__ void fma2(unsigned long long& c, unsigned long long a,
                                     unsigned long long b) {
    asm("fma.rn.f32x2 %0, %1, %2, %0;" : "+l"(c) : "l"(a), "l"(b));
}
__device__ __forceinline__ unsigned long long dup2(float x) {
    unsigned long long r;
    unsigned int xi = __float_as_uint(x);
    asm("mov.b64 %0, {%1, %1};" : "=l"(r) : "r"(xi));
    return r;
}

// ============================================================================
// Kernel 1: u = x @ U^T  (per-CTA: 64 rows x all 64 r), then
//           g_h init = u @ bm.reshape(64,64)  (the +bm term of the einsum).
// ============================================================================
__global__ __launch_bounds__(256, 2)
void u_init_kernel(const float* __restrict__ Xext, int xsel,
                   const float* __restrict__ U, const float* __restrict__ bm) {
    const float* X = in_sel(Xext, xsel);
    __shared__ float sb[4352];   // Xs[32][68] | Us[32][68]; later u_sm[64][65]
    const int tid = threadIdx.x;
    const int m0 = blockIdx.x * 64;
    const int tx = tid & 15, ty = tid >> 4;

    float acc[4][4] = {};
    for (int k0 = 0; k0 < Din; k0 += 32) {
#pragma unroll
        for (int it = 0; it < 2; ++it) {
            int t = tid + it * 256;
            int row = t >> 3, quad = t & 7;
            float4 v = *reinterpret_cast<const float4*>(
                X + (size_t)(m0 + row) * Din + k0 + quad * 4);
            sb[(quad * 4 + 0) * 68 + row] = v.x;
            sb[(quad * 4 + 1) * 68 + row] = v.y;
            sb[(quad * 4 + 2) * 68 + row] = v.z;
            sb[(quad * 4 + 3) * 68 + row] = v.w;
            float4 w = *reinterpret_cast<const float4*>(
                U + (size_t)row * Din + k0 + quad * 4);
            sb[2176 + (quad * 4 + 0) * 68 + row] = w.x;
            sb[2176 + (quad * 4 + 1) * 68 + row] = w.y;
            sb[2176 + (quad * 4 + 2) * 68 + row] = w.z;
            sb[2176 + (quad * 4 + 3) * 68 + row] = w.w;
        }
        __syncthreads();
#pragma unroll
        for (int k = 0; k < 32; ++k) {
            float a[4], b[4];
#pragma unroll
            for (int i = 0; i < 4; ++i) a[i] = sb[k * 68 + ty * 4 + i];
#pragma unroll
            for (int j = 0; j < 4; ++j) b[j] = sb[2176 + k * 68 + tx * 4 + j];
#pragma unroll
            for (int i = 0; i < 4; ++i)
#pragma unroll
                for (int j = 0; j < 4; ++j) acc[i][j] += a[i] * b[j];
        }
        __syncthreads();
    }

    // Write u to global and stage the full 64x64 u tile in smem.
#pragma unroll
    for (int i = 0; i < 4; ++i)
#pragma unroll
        for (int j = 0; j < 4; ++j) {
            g_u[(size_t)(m0 + ty * 4 + i) * Rk + tx * 4 + j] = acc[i][j];
            sb[(ty * 4 + i) * 65 + tx * 4 + j] = acc[i][j];
        }
    __syncthreads();

    // hinit[b][s] = sum_r u[b][r] * bm[r*64+s]   (bm term of h; also serves as
    // the zero-init for the atomic reduction in the main kernel).
    float hin[4][4] = {};
#pragma unroll 4
    for (int r = 0; r < 64; ++r) {
        float bv[4];
#pragma unroll
        for (int j = 0; j < 4; ++j) bv[j] = __ldg(bm + r * 64 + tx * 4 + j);
#pragma unroll
        for (int i = 0; i < 4; ++i) {
            float uv = sb[(ty * 4 + i) * 65 + r];
#pragma unroll
            for (int j = 0; j < 4; ++j) hin[i][j] += uv * bv[j];
        }
    }
#pragma unroll
    for (int i = 0; i < 4; ++i)
#pragma unroll
        for (int j = 0; j < 4; ++j)
            g_h[(size_t)(m0 + ty * 4 + i) * Rk + tx * 4 + j] = hin[i][j];
}

// ============================================================================
// Kernel 2: big GEMM C = X @ Wm^T with fused einsum epilogue:
//   h[b,s] += sum_{r in this N-tile} u[b,r] * C[b, r*64+s]
// Tile 128x128, Ktile 32, 256 threads, 8x8 microtile via fma.rn.f32x2.
// Grid: (RS/128 = 32, Bsz/128 = 64)
// ============================================================================
__global__ __launch_bounds__(256, 2)
void apg_main_kernel(const float* __restrict__ Xext, int xsel,
                     const float* __restrict__ Wm) {
    const float* X = in_sel(Xext, xsel);
    __shared__ float sb[8448];   // As[32][132] | Bs[32][132]; later hpart+u
    const int tid = threadIdx.x;
    const int m0 = blockIdx.y * 128;
    const int n0 = blockIdx.x * 128;
    const int tx = tid & 15, ty = tid >> 4;

    unsigned long long acc2[4][8];   // rows paired: (ty*8+2*i2, +1) x col tx*8+j
#pragma unroll
    for (int i = 0; i < 4; ++i)
#pragma unroll
        for (int j = 0; j < 8; ++j) acc2[i][j] = 0ull;

    for (int k0 = 0; k0 < Din; k0 += 32) {
#pragma unroll
        for (int it = 0; it < 4; ++it) {
            int t = tid + it * 256;
            int row = t >> 3, quad = t & 7;
            float4 v = *reinterpret_cast<const float4*>(
                X + (size_t)(m0 + row) * Din + k0 + quad * 4);
            sb[(quad * 4 + 0) * 132 + row] = v.x;
            sb[(quad * 4 + 1) * 132 + row] = v.y;
            sb[(quad * 4 + 2) * 132 + row] = v.z;
            sb[(quad * 4 + 3) * 132 + row] = v.w;
            float4 w = *reinterpret_cast<const float4*>(
                Wm + (size_t)(n0 + row) * Din + k0 + quad * 4);
            sb[4224 + (quad * 4 + 0) * 132 + row] = w.x;
            sb[4224 + (quad * 4 + 1) * 132 + row] = w.y;
            sb[4224 + (quad * 4 + 2) * 132 + row] = w.z;
            sb[4224 + (quad * 4 + 3) * 132 + row] = w.w;
        }
        __syncthreads();
#pragma unroll
        for (int k = 0; k < 32; ++k) {
            const float* Ak = sb + k * 132 + ty * 8;
            const float* Bk = sb + 4224 + k * 132 + tx * 8;
            unsigned long long a2[4];
#pragma unroll
            for (int i2 = 0; i2 < 4; ++i2)
                a2[i2] = *reinterpret_cast<const unsigned long long*>(Ak + i2 * 2);
            float4 b0 = *reinterpret_cast<const float4*>(Bk);
            float4 b1 = *reinterpret_cast<const float4*>(Bk + 4);
            unsigned long long b2[8];
            b2[0] = dup2(b0.x); b2[1] = dup2(b0.y);
            b2[2] = dup2(b0.z); b2[3] = dup2(b0.w);
            b2[4] = dup2(b1.x); b2[5] = dup2(b1.y);
            b2[6] = dup2(b1.z); b2[7] = dup2(b1.w);
#pragma unroll
            for (int i2 = 0; i2 < 4; ++i2)
#pragma unroll
                for (int j = 0; j < 8; ++j) fma2(acc2[i2][j], a2[i2], b2[j]);
        }
        __syncthreads();
    }

    // ---- fused einsum epilogue ----
    // Unpack accumulators.
    float acc[8][8];
#pragma unroll
    for (int i2 = 0; i2 < 4; ++i2)
#pragma unroll
        for (int j = 0; j < 8; ++j) {
            float2 f = *reinterpret_cast<float2*>(&acc2[i2][j]);
            acc[2 * i2 + 0][j] = f.x;
            acc[2 * i2 + 1][j] = f.y;
        }

    float* hp = sb;        // hpart[128][64] = 8192 floats
    float* us = sb + 8192; // u[128 rows][2 r] = 256 floats
    const int r0 = n0 >> 6;
    us[tid] = g_u[(size_t)(m0 + (tid >> 1)) * Rk + r0 + (tid & 1)];
    __syncthreads();

    if (tx < 8) {   // cols 0..63 -> r = r0, s = tx*8+j (unique writer per (m,s))
#pragma unroll
        for (int i = 0; i < 8; ++i) {
            int m = ty * 8 + i;
            float uv = us[m * 2 + 0];
#pragma unroll
            for (int j = 0; j < 8; ++j) hp[m * 64 + tx * 8 + j] = acc[i][j] * uv;
        }
    }
    __syncthreads();
    if (tx >= 8) {  // cols 64..127 -> r = r0+1, s = (tx-8)*8+j
#pragma unroll
        for (int i = 0; i < 8; ++i) {
            int m = ty * 8 + i;
            float uv = us[m * 2 + 1];
#pragma unroll
            for (int j = 0; j < 8; ++j)
                hp[m * 64 + (tx - 8) * 8 + j] += acc[i][j] * uv;
        }
    }
    __syncthreads();

    // Coalesced atomic accumulation into g_h (16 N-tiles contend per element).
#pragma unroll
    for (int i = 0; i < 32; ++i) {
        int idx = tid + i * 256;   // m = idx>>6, s = idx&63
        atomicAdd(&g_h[(size_t)m0 * Rk + idx], hp[idx]);
    }
}

// ============================================================================
// Kernel 3: out = h @ V^T + bias (+ optional ReLU).  Tile 128x128, K=64.
// Grid: (Din/128 = 8, Bsz/128 = 64)
// ============================================================================
__global__ __launch_bounds__(256, 2)
void apg_out_kernel(const float* __restrict__ V, const float* __restrict__ bias,
                    float* __restrict__ Oext, int osel, int relu) {
    float* O = out_sel(Oext, osel);
    __shared__ float sb[8448];
    const int tid = threadIdx.x;
    const int m0 = blockIdx.y * 128;
    const int n0 = blockIdx.x * 128;
    const int tx = tid & 15, ty = tid >> 4;

    float acc[8][8] = {};
    for (int k0 = 0; k0 < Rk; k0 += 32) {
#pragma unroll
        for (int it = 0; it < 4; ++it) {
            int t = tid + it * 256;
            int row = t >> 3, quad = t & 7;
            float4 v = *reinterpret_cast<const float4*>(
                g_h + (size_t)(m0 + row) * Rk + k0 + quad * 4);
            sb[(quad * 4 + 0) * 132 + row] = v.x;
            sb[(quad * 4 + 1) * 132 + row] = v.y;
            sb[(quad * 4 + 2) * 132 + row] = v.z;
            sb[(quad * 4 + 3) * 132 + row] = v.w;
            float4 w = *reinterpret_cast<const float4*>(
                V + (size_t)(n0 + row) * Rk + k0 + quad * 4);
            sb[4224 + (quad * 4 + 0) * 132 + row] = w.x;
            sb[4224 + (quad * 4 + 1) * 132 + row] = w.y;
            sb[4224 + (quad * 4 + 2) * 132 + row] = w.z;
            sb[4224 + (quad * 4 + 3) * 132 + row] = w.w;
        }
        __syncthreads();
#pragma unroll
        for (int k = 0; k < 32; ++k) {
            float a[8], b[8];
            float4 a0 = *reinterpret_cast<const float4*>(sb + k * 132 + ty * 8);
            float4 a1 = *reinterpret_cast<const float4*>(sb + k * 132 + ty * 8 + 4);
            float4 b0 = *reinterpret_cast<const float4*>(sb + 4224 + k * 132 + tx * 8);
            float4 b1 = *reinterpret_cast<const float4*>(sb + 4224 + k * 132 + tx * 8 + 4);
            a[0] = a0.x; a[1] = a0.y; a[2] = a0.z; a[3] = a0.w;
            a[4] = a1.x; a[5] = a1.y; a[6] = a1.z; a[7] = a1.w;
            b[0] = b0.x; b[1] = b0.y; b[2] = b0.z; b[3] = b0.w;
            b[4] = b1.x; b[5] = b1.y; b[6] = b1.z; b[7] = b1.w;
#pragma unroll
            for (int i = 0; i < 8; ++i)
#pragma unroll
                for (int j = 0; j < 8; ++j) acc[i][j] += a[i] * b[j];
        }
        __syncthreads();
    }

    float4 bv0 = *reinterpret_cast<const float4*>(bias + n0 + tx * 8);
    float4 bv1 = *reinterpret_cast<const float4*>(bias + n0 + tx * 8 + 4);
    float bb[8] = {bv0.x, bv0.y, bv0.z, bv0.w, bv1.x, bv1.y, bv1.z, bv1.w};
#pragma unroll
    for (int i = 0; i < 8; ++i) {
        float v[8];
#pragma unroll
        for (int j = 0; j < 8; ++j) {
            v[j] = acc[i][j] + bb[j];
            if (relu) v[j] = fmaxf(v[j], 0.0f);
        }
        float4* dst = reinterpret_cast<float4*>(
            O + (size_t)(m0 + ty * 8 + i) * Din + n0 + tx * 8);
        dst[0] = make_float4(v[0], v[1], v[2], v[3]);
        dst[1] = make_float4(v[4], v[5], v[6], v[7]);
    }
}

// ============================================================================
// Launch: 3 layers x (u_init -> main GEMM+reduce -> out GEMM)
// ============================================================================
static void run_layer(const float* xext, int xsel,
                      const float* Wm, const float* bm, const float* U,
                      const float* V, const float* bias,
                      float* oext, int osel, int relu) {
    u_init_kernel<<<Bsz / 64, 256>>>(xext, xsel, U, bm);
    apg_main_kernel<<<dim3(RS / 128, Bsz / 128), 256>>>(xext, xsel, Wm);
    apg_out_kernel<<<dim3(Din / 128, Bsz / 128), 256>>>(V, bias, oext, osel, relu);
}

extern "C" void kernel_launch(void* const* d_in, const int* in_sizes, int n_in,
                              void* d_out, int out_size) {
    const float* x = (const float*)d_in[0];
    // layer 0: x (ext) -> g_act0, ReLU
    run_layer(x, 2,
              (const float*)d_in[1], (const float*)d_in[2], (const float*)d_in[3],
              (const float*)d_in[4], (const float*)d_in[5],
              nullptr, 0, 1);
    // layer 1: g_act0 -> g_act1, ReLU
    run_layer(nullptr, 0,
              (const float*)d_in[6], (const float*)d_in[7], (const float*)d_in[8],
              (const float*)d_in[9], (const float*)d_in[10],
              nullptr, 1, 1);
    // layer 2: g_act1 -> d_out, no activation
    run_layer(nullptr, 1,
              (const float*)d_in[11], (const float*)d_in[12], (const float*)d_in[13],
              (const float*)d_in[14], (const float*)d_in[15],
              (float*)d_out, 2, 0);
}

// round 5
// speedup vs baseline: 1.4008x; 1.4008x over previous
#include <cuda_runtime.h>
#include <cuda_bf16.h>
#include <cstdint>

// Problem constants
#define Bsz 8192
#define Din 1024
#define Rk  64

// ---------------------------------------------------------------------------
// Scratch (__device__ globals; cudaMalloc forbidden)
// ---------------------------------------------------------------------------
__device__ float g_u[Bsz * Rk];          // 2 MB   u = x @ U^T (per layer)
__device__ float g_h[Bsz * Rk];          // 2 MB   h_gemm accumulator
__device__ float g_act0[Bsz * Din];      // 32 MB
__device__ float g_act1[Bsz * Din];      // 32 MB
__device__ float g_Vx[Din * 128];        // 512 KB fused [V | (bm@V^T)^T] weights

__device__ __forceinline__ const float* in_sel(const float* ext, int sel) {
    if (sel == 0) return g_act0;
    if (sel == 1) return g_act1;
    return ext;
}
__device__ __forceinline__ float* out_sel(float* ext, int sel) {
    if (sel == 0) return g_act0;
    if (sel == 1) return g_act1;
    return ext;
}

// ---------------------------------------------------------------------------
// PTX helpers (baseline sm_80-class PTX only — harness targets plain sm_103)
// ---------------------------------------------------------------------------
__device__ __forceinline__ uint32_t smem_u32(const void* p) {
    uint32_t a;
    asm("{ .reg .u64 t; cvta.to.shared.u64 t, %1; cvt.u32.u64 %0, t; }"
        : "=r"(a) : "l"(p));
    return a;
}
#define CPASYNC16(saddr, gptr) \
    asm volatile("cp.async.cg.shared.global [%0], [%1], 16;" \
                 :: "r"(saddr), "l"(gptr) : "memory")
#define CP_COMMIT() asm volatile("cp.async.commit_group;" ::: "memory")
#define CP_WAIT1()  asm volatile("cp.async.wait_group 1;" ::: "memory")

#define LDM4(r, addr) \
    asm volatile("ldmatrix.sync.aligned.m8n8.x4.shared.b16 {%0,%1,%2,%3}, [%4];" \
                 : "=r"((r)[0]), "=r"((r)[1]), "=r"((r)[2]), "=r"((r)[3]) \
                 : "r"(addr))

#define MMA16816(d, a, b) \
    asm volatile("mma.sync.aligned.m16n8k16.row.col.f32.bf16.bf16.f32 " \
                 "{%0,%1,%2,%3}, {%4,%5,%6,%7}, {%8,%9}, {%0,%1,%2,%3};" \
                 : "+f"((d)[0]), "+f"((d)[1]), "+f"((d)[2]), "+f"((d)[3]) \
                 : "r"((a)[0]), "r"((a)[1]), "r"((a)[2]), "r"((a)[3]), \
                   "r"((b)[0]), "r"((b)[1]))

// ---------------------------------------------------------------------------
// Shared-memory layout of the MMA kernel (bytes)
// ---------------------------------------------------------------------------
#define FB_PITCH 68                         // fp32 staging pitch (floats)
#define FB_STAGE (256 * FB_PITCH * 4)       // 69632 B (X rows 0-127, W rows 128-255)
#define BB_PITCH 72                         // bf16 tile pitch (elems) -> 144 B rows
#define BB_BYTES (128 * BB_PITCH * 2)       // 18432 B per matrix
#define OFF_AH   (2 * FB_STAGE)             // 139264
#define OFF_AL   (OFF_AH + BB_BYTES)
#define OFF_BH   (OFF_AH + 2 * BB_BYTES)
#define OFF_BL   (OFF_AH + 3 * BB_BYTES)
#define OFF_U    (OFF_AH + 4 * BB_BYTES)    // 212992, U slice 2x1024 fp32 = 8192 B
#define OFF_UP   (OFF_U + 8192)             // u partials 128*2*2*4 = 2048 B
#define OFF_UF   (OFF_UP + 2048)            // u final 128*2*4 = 1024 B
#define SMEM_MMA (OFF_UF + 1024)            // 224256 B

// ---------------------------------------------------------------------------
// zero g_h (h accumulates via atomics)
// ---------------------------------------------------------------------------
__global__ void zero_h_kernel() {
    int i = blockIdx.x * 256 + threadIdx.x;
    reinterpret_cast<float4*>(g_h)[i] = make_float4(0.f, 0.f, 0.f, 0.f);
}

// ---------------------------------------------------------------------------
// g_Vx[o][0:64] = V[o][:],  g_Vx[o][64+r] = sum_s bm[r*64+s] * V[o][s]
// (folds the "+bm" hyper-net bias through the einsum and V)
// ---------------------------------------------------------------------------
__global__ __launch_bounds__(128)
void w2v_kernel(const float* __restrict__ V, const float* __restrict__ bm) {
    __shared__ float Vrow[64];
    __shared__ float bms[4096];
    const int o = blockIdx.x, t = threadIdx.x;
    for (int j = t; j < 4096; j += 128) bms[j] = bm[j];
    if (t < 64) Vrow[t] = V[o * 64 + t];
    __syncthreads();
    if (t < 64) {
        g_Vx[o * 128 + t] = Vrow[t];
    } else {
        const int r = t - 64;
        float s = 0.f;
#pragma unroll
        for (int ss = 0; ss < 64; ++ss) s = fmaf(bms[r * 64 + ss], Vrow[ss], s);
        g_Vx[o * 128 + 64 + r] = s;
    }
}

// ---------------------------------------------------------------------------
// Main fused kernel: C = X @ Wm^T via bf16 HMMA 3-term split, fp32->bf16
// conversion in-kernel, u = X @ U^T (exact fp32) computed from the staged
// fp32 tiles, epilogue h[m,s] += sum_r u_r * C[m, r*64+s] via atomics.
// CTA tile M=128, N=128, K-chunk 64. grid = (32 n-tiles, 64 m-tiles).
// ---------------------------------------------------------------------------
__global__ __launch_bounds__(256, 1)
void apg_mma_kernel(const float* __restrict__ Xext, int xsel,
                    const float* __restrict__ Wm, const float* __restrict__ Uu) {
    extern __shared__ __align__(16) char sm[];
    const float* X = in_sel(Xext, xsel);
    const int t = threadIdx.x, lane = t & 31, w = t >> 5;
    const int mw = w >> 2, nw = w & 3;           // warp grid 2 (M) x 4 (N)
    const int nb = blockIdx.x, mb = blockIdx.y;
    const uint32_t smb = smem_u32(sm);
    float* fb32 = reinterpret_cast<float*>(sm);

    // per-thread staging coords: row lr (0-127), k-half lhalf (0/1)
    const int lr = t & 127, lhalf = t >> 7;
    const float* gX = X + (size_t)(mb * 128 + lr) * Din + lhalf * 32;
    const float* gW = Wm + (size_t)(nb * 128 + lr) * Din + lhalf * 32;
    const uint32_t sx_base = smb + (lr * FB_PITCH + lhalf * 32) * 4;

    auto issue = [&](int chunk, int stg) {
        const float* gx = gX + chunk * 64;
        const float* gw = gW + chunk * 64;
        uint32_t sx = sx_base + stg * FB_STAGE;
        uint32_t sw = sx + 128 * FB_PITCH * 4;
#pragma unroll
        for (int j = 0; j < 8; ++j) {
            CPASYNC16(sx + j * 16, gx + j * 4);
            CPASYNC16(sw + j * 16, gw + j * 4);
        }
    };

    // prologue: chunk 0 + U slice (2 r-rows of 1024)
    issue(0, 0);
    CP_COMMIT();
    {
        const float4* gU4 = reinterpret_cast<const float4*>(Uu + (size_t)(2 * nb) * Din);
        float4* usm = reinterpret_cast<float4*>(sm + OFF_U);
        usm[t] = gU4[t];
        usm[t + 256] = gU4[t + 256];
    }

    float uacc0 = 0.f, uacc1 = 0.f;
    float acc[4][4][4];
#pragma unroll
    for (int i = 0; i < 4; ++i)
#pragma unroll
        for (int j = 0; j < 4; ++j)
#pragma unroll
            for (int e = 0; e < 4; ++e) acc[i][j][e] = 0.f;

    // static ldmatrix lane offsets
    const int arow = lane & 15, acol = (lane >> 4) * 8;
    const int brow = ((lane >> 4) << 3) + (lane & 7), bcol = ((lane >> 3) & 1) * 8;

    for (int i = 0; i < 16; ++i) {
        const int cur = i & 1;
        if (i < 15) issue(i + 1, cur ^ 1);
        CP_COMMIT();
        CP_WAIT1();
        __syncthreads();                     // chunk i staged; prev MMA done

        // ---- convert fp32 chunk -> bf16 hi/lo tiles; accumulate u ----
        {
            const float* fx = fb32 + cur * (FB_STAGE / 4) + lr * FB_PITCH + lhalf * 32;
            const float* fw = fx + 128 * FB_PITCH;
            const float* Us0 = reinterpret_cast<const float*>(sm + OFF_U) + i * 64 + lhalf * 32;
            const float* Us1 = Us0 + 1024;
            char* dAh = sm + OFF_AH + lr * 144 + lhalf * 64;
            char* dAl = sm + OFF_AL + lr * 144 + lhalf * 64;
            char* dBh = sm + OFF_BH + lr * 144 + lhalf * 64;
            char* dBl = sm + OFF_BL + lr * 144 + lhalf * 64;
            const float4* s4 = reinterpret_cast<const float4*>(fx);
#pragma unroll
            for (int g = 0; g < 8; ++g) {
                float4 v = s4[g];
                __nv_bfloat16 h0 = __float2bfloat16_rn(v.x), h1 = __float2bfloat16_rn(v.y);
                __nv_bfloat16 h2 = __float2bfloat16_rn(v.z), h3 = __float2bfloat16_rn(v.w);
                float l0 = v.x - __bfloat162float(h0), l1 = v.y - __bfloat162float(h1);
                float l2 = v.z - __bfloat162float(h2), l3 = v.w - __bfloat162float(h3);
                uint2 hp2, lp2;
                hp2.x = (uint32_t)__bfloat16_as_ushort(h0) |
                        ((uint32_t)__bfloat16_as_ushort(h1) << 16);
                hp2.y = (uint32_t)__bfloat16_as_ushort(h2) |
                        ((uint32_t)__bfloat16_as_ushort(h3) << 16);
                __nv_bfloat162 lo01 = __floats2bfloat162_rn(l0, l1);
                __nv_bfloat162 lo23 = __floats2bfloat162_rn(l2, l3);
                lp2.x = *reinterpret_cast<uint32_t*>(&lo01);
                lp2.y = *reinterpret_cast<uint32_t*>(&lo23);
                *reinterpret_cast<uint2*>(dAh + g * 8) = hp2;
                *reinterpret_cast<uint2*>(dAl + g * 8) = lp2;
                uacc0 = fmaf(v.x, Us0[g * 4 + 0], uacc0);
                uacc0 = fmaf(v.y, Us0[g * 4 + 1], uacc0);
                uacc0 = fmaf(v.z, Us0[g * 4 + 2], uacc0);
                uacc0 = fmaf(v.w, Us0[g * 4 + 3], uacc0);
                uacc1 = fmaf(v.x, Us1[g * 4 + 0], uacc1);
                uacc1 = fmaf(v.y, Us1[g * 4 + 1], uacc1);
                uacc1 = fmaf(v.z, Us1[g * 4 + 2], uacc1);
                uacc1 = fmaf(v.w, Us1[g * 4 + 3], uacc1);
            }
            const float4* w4 = reinterpret_cast<const float4*>(fw);
#pragma unroll
            for (int g = 0; g < 8; ++g) {
                float4 v = w4[g];
                __nv_bfloat16 h0 = __float2bfloat16_rn(v.x), h1 = __float2bfloat16_rn(v.y);
                __nv_bfloat16 h2 = __float2bfloat16_rn(v.z), h3 = __float2bfloat16_rn(v.w);
                float l0 = v.x - __bfloat162float(h0), l1 = v.y - __bfloat162float(h1);
                float l2 = v.z - __bfloat162float(h2), l3 = v.w - __bfloat162float(h3);
                uint2 hp2, lp2;
                hp2.x = (uint32_t)__bfloat16_as_ushort(h0) |
                        ((uint32_t)__bfloat16_as_ushort(h1) << 16);
                hp2.y = (uint32_t)__bfloat16_as_ushort(h2) |
                        ((uint32_t)__bfloat16_as_ushort(h3) << 16);
                __nv_bfloat162 lo01 = __floats2bfloat162_rn(l0, l1);
                __nv_bfloat162 lo23 = __floats2bfloat162_rn(l2, l3);
                lp2.x = *reinterpret_cast<uint32_t*>(&lo01);
                lp2.y = *reinterpret_cast<uint32_t*>(&lo23);
                *reinterpret_cast<uint2*>(dBh + g * 8) = hp2;
                *reinterpret_cast<uint2*>(dBl + g * 8) = lp2;
            }
        }
        __syncthreads();                     // bf16 tiles ready

        // ---- 3-term MMA over the 64-k chunk (4 k16 steps) ----
#pragma unroll
        for (int ks = 0; ks < 4; ++ks) {
            uint32_t ah[4][4], al[4][4], bh[4][2], bl[4][2];
#pragma unroll
            for (int mt = 0; mt < 4; ++mt) {
                uint32_t off = ((mw * 64 + mt * 16 + arow) * BB_PITCH + ks * 16 + acol) * 2;
                LDM4(ah[mt], smb + OFF_AH + off);
                LDM4(al[mt], smb + OFF_AL + off);
            }
#pragma unroll
            for (int p = 0; p < 2; ++p) {
                uint32_t off = ((nw * 32 + p * 16 + brow) * BB_PITCH + ks * 16 + bcol) * 2;
                uint32_t r0[4], r1[4];
                LDM4(r0, smb + OFF_BH + off);
                bh[2 * p][0] = r0[0]; bh[2 * p][1] = r0[1];
                bh[2 * p + 1][0] = r0[2]; bh[2 * p + 1][1] = r0[3];
                LDM4(r1, smb + OFF_BL + off);
                bl[2 * p][0] = r1[0]; bl[2 * p][1] = r1[1];
                bl[2 * p + 1][0] = r1[2]; bl[2 * p + 1][1] = r1[3];
            }
#pragma unroll
            for (int mt = 0; mt < 4; ++mt)
#pragma unroll
                for (int nt = 0; nt < 4; ++nt) {
                    MMA16816(acc[mt][nt], ah[mt], bh[nt]);   // hi*hi
                    MMA16816(acc[mt][nt], ah[mt], bl[nt]);   // hi*lo
                    MMA16816(acc[mt][nt], al[mt], bh[nt]);   // lo*hi
                }
        }
    }

    // ---- finalize u (combine k-halves across the two thread groups) ----
    {
        float* up = reinterpret_cast<float*>(sm + OFF_UP);
        up[lr * 4 + 0 + lhalf] = uacc0;       // [r][rr=0][half]
        up[lr * 4 + 2 + lhalf] = uacc1;       // [r][rr=1][half]
    }
    __syncthreads();
    if (t < 128) {
        const float* up = reinterpret_cast<const float*>(sm + OFF_UP);
        float u0 = up[t * 4 + 0] + up[t * 4 + 1];
        float u1 = up[t * 4 + 2] + up[t * 4 + 3];
        float* uf = reinterpret_cast<float*>(sm + OFF_UF);
        uf[t * 2 + 0] = u0;
        uf[t * 2 + 1] = u1;
        g_u[(size_t)(mb * 128 + t) * Rk + 2 * nb + 0] = u0;
        g_u[(size_t)(mb * 128 + t) * Rk + 2 * nb + 1] = u1;
    }
    __syncthreads();

    // ---- epilogue: hp[m][s] = u0*C(:, s) + u1*C(:, 64+s), two phases ----
    float* hp = reinterpret_cast<float*>(sm);                 // reuse staging
    const float* uf = reinterpret_cast<const float*>(sm + OFF_UF);
    const int mbase = mw * 64, scol = (nw & 1) * 32;
    if (nw < 2) {
#pragma unroll
        for (int mt = 0; mt < 4; ++mt)
#pragma unroll
            for (int nt = 0; nt < 4; ++nt) {
                int m0 = mbase + mt * 16 + (lane >> 2);
                int s0 = scol + nt * 8 + 2 * (lane & 3);
                hp[m0 * 65 + s0]       = acc[mt][nt][0] * uf[m0 * 2];
                hp[m0 * 65 + s0 + 1]   = acc[mt][nt][1] * uf[m0 * 2];
                hp[(m0 + 8) * 65 + s0]     = acc[mt][nt][2] * uf[(m0 + 8) * 2];
                hp[(m0 + 8) * 65 + s0 + 1] = acc[mt][nt][3] * uf[(m0 + 8) * 2];
            }
    }
    __syncthreads();
    if (nw >= 2) {
#pragma unroll
        for (int mt = 0; mt < 4; ++mt)
#pragma unroll
            for (int nt = 0; nt < 4; ++nt) {
                int m0 = mbase + mt * 16 + (lane >> 2);
                int s0 = scol + nt * 8 + 2 * (lane & 3);
                hp[m0 * 65 + s0]       += acc[mt][nt][0] * uf[m0 * 2 + 1];
                hp[m0 * 65 + s0 + 1]   += acc[mt][nt][1] * uf[m0 * 2 + 1];
                hp[(m0 + 8) * 65 + s0]     += acc[mt][nt][2] * uf[(m0 + 8) * 2 + 1];
                hp[(m0 + 8) * 65 + s0 + 1] += acc[mt][nt][3] * uf[(m0 + 8) * 2 + 1];
            }
    }
    __syncthreads();

    float* dst = g_h + (size_t)mb * 128 * Rk;
#pragma unroll 8
    for (int ii = 0; ii < 32; ++ii) {
        int idx = ii * 256 + t;               // m = idx>>6, s = idx&63
        atomicAdd(dst + idx, hp[(idx >> 6) * 65 + (idx & 63)]);
    }
}

// ---------------------------------------------------------------------------
// out = [h | u] @ [V | W2]^T + b (+ ReLU).  K=128.  grid (8, 64), 256 thr.
// ---------------------------------------------------------------------------
__global__ __launch_bounds__(256, 2)
void apg_out_kernel(const float* __restrict__ bias,
                    float* __restrict__ Oext, int osel, int relu) {
    float* O = out_sel(Oext, osel);
    __shared__ float sb[8448];
    const int tid = threadIdx.x;
    const int m0 = blockIdx.y * 128;
    const int n0 = blockIdx.x * 128;
    const int tx = tid & 15, ty = tid >> 4;

    float acc[8][8] = {};
    for (int k0 = 0; k0 < 128; k0 += 32) {
        const float* Asrc = (k0 < 64) ? g_h : g_u;
        const int kk = k0 & 63;
#pragma unroll
        for (int it = 0; it < 4; ++it) {
            int t = tid + it * 256;
            int row = t >> 3, quad = t & 7;
            float4 v = *reinterpret_cast<const float4*>(
                Asrc + (size_t)(m0 + row) * Rk + kk + quad * 4);
            sb[(quad * 4 + 0) * 132 + row] = v.x;
            sb[(quad * 4 + 1) * 132 + row] = v.y;
            sb[(quad * 4 + 2) * 132 + row] = v.z;
            sb[(quad * 4 + 3) * 132 + row] = v.w;
            float4 w = *reinterpret_cast<const float4*>(
                g_Vx + (size_t)(n0 + row) * 128 + k0 + quad * 4);
            sb[4224 + (quad * 4 + 0) * 132 + row] = w.x;
            sb[4224 + (quad * 4 + 1) * 132 + row] = w.y;
            sb[4224 + (quad * 4 + 2) * 132 + row] = w.z;
            sb[4224 + (quad * 4 + 3) * 132 + row] = w.w;
        }
        __syncthreads();
#pragma unroll
        for (int k = 0; k < 32; ++k) {
            float a[8], b[8];
            float4 a0 = *reinterpret_cast<const float4*>(sb + k * 132 + ty * 8);
            float4 a1 = *reinterpret_cast<const float4*>(sb + k * 132 + ty * 8 + 4);
            float4 b0 = *reinterpret_cast<const float4*>(sb + 4224 + k * 132 + tx * 8);
            float4 b1 = *reinterpret_cast<const float4*>(sb + 4224 + k * 132 + tx * 8 + 4);
            a[0] = a0.x; a[1] = a0.y; a[2] = a0.z; a[3] = a0.w;
            a[4] = a1.x; a[5] = a1.y; a[6] = a1.z; a[7] = a1.w;
            b[0] = b0.x; b[1] = b0.y; b[2] = b0.z; b[3] = b0.w;
            b[4] = b1.x; b[5] = b1.y; b[6] = b1.z; b[7] = b1.w;
#pragma unroll
            for (int i = 0; i < 8; ++i)
#pragma unroll
                for (int j = 0; j < 8; ++j) acc[i][j] += a[i] * b[j];
        }
        __syncthreads();
    }

    float4 bv0 = *reinterpret_cast<const float4*>(bias + n0 + tx * 8);
    float4 bv1 = *reinterpret_cast<const float4*>(bias + n0 + tx * 8 + 4);
    float bb[8] = {bv0.x, bv0.y, bv0.z, bv0.w, bv1.x, bv1.y, bv1.z, bv1.w};
#pragma unroll
    for (int i = 0; i < 8; ++i) {
        float v[8];
#pragma unroll
        for (int j = 0; j < 8; ++j) {
            v[j] = acc[i][j] + bb[j];
            if (relu) v[j] = fmaxf(v[j], 0.0f);
        }
        float4* dst = reinterpret_cast<float4*>(
            O + (size_t)(m0 + ty * 8 + i) * Din + n0 + tx * 8);
        dst[0] = make_float4(v[0], v[1], v[2], v[3]);
        dst[1] = make_float4(v[4], v[5], v[6], v[7]);
    }
}

// ---------------------------------------------------------------------------
// Launch
// ---------------------------------------------------------------------------
static void run_layer(const float* xext, int xsel,
                      const float* Wm, const float* bm, const float* U,
                      const float* V, const float* bias,
                      float* oext, int osel, int relu) {
    zero_h_kernel<<<512, 256>>>();
    w2v_kernel<<<Din, 128>>>(V, bm);
    apg_mma_kernel<<<dim3(32, 64), 256, SMEM_MMA>>>(xext, xsel, Wm, U);
    apg_out_kernel<<<dim3(8, 64), 256>>>(bias, oext, osel, relu);
}

extern "C" void kernel_launch(void* const* d_in, const int* in_sizes, int n_in,
                              void* d_out, int out_size) {
    cudaFuncSetAttribute(apg_mma_kernel,
                         cudaFuncAttributeMaxDynamicSharedMemorySize, SMEM_MMA);
    const float* x = (const float*)d_in[0];
    run_layer(x, 2,
              (const float*)d_in[1], (const float*)d_in[2], (const float*)d_in[3],
              (const float*)d_in[4], (const float*)d_in[5],
              nullptr, 0, 1);
    run_layer(nullptr, 0,
              (const float*)d_in[6], (const float*)d_in[7], (const float*)d_in[8],
              (const float*)d_in[9], (const float*)d_in[10],
              nullptr, 1, 1);
    run_layer(nullptr, 1,
              (const float*)d_in[11], (const float*)d_in[12], (const float*)d_in[13],
              (const float*)d_in[14], (const float*)d_in[15],
              (float*)d_out, 2, 0);
}

// round 6
// speedup vs baseline: 2.3933x; 1.7085x over previous
#include <cuda_runtime.h>
#include <cuda_bf16.h>
#include <cstdint>

// Problem constants
#define Bsz 8192
#define Din 1024
#define Rk  64

// ---------------------------------------------------------------------------
// Scratch (__device__ globals; cudaMalloc forbidden)
// ---------------------------------------------------------------------------
__device__ float g_u[Bsz * Rk];          // 2 MB
__device__ float g_h[Bsz * Rk];          // 2 MB
__device__ float g_act0[Bsz * Din];      // 32 MB
__device__ float g_act1[Bsz * Din];      // 32 MB
__device__ float g_Vx[Din * 128];        // 512 KB  [V | (bm@V^T)^T]
// bf16 hi/lo planes (written once per layer; L2-resident during GEMM)
__device__ __align__(16) __nv_bfloat16 g_Ah[(size_t)Bsz * Din];   // 16 MB
__device__ __align__(16) __nv_bfloat16 g_Al[(size_t)Bsz * Din];   // 16 MB
__device__ __align__(16) __nv_bfloat16 g_Bh[(size_t)4096 * Din];  // 8 MB
__device__ __align__(16) __nv_bfloat16 g_Bl[(size_t)4096 * Din];  // 8 MB

__device__ __forceinline__ const float* in_sel(const float* ext, int sel) {
    if (sel == 0) return g_act0;
    if (sel == 1) return g_act1;
    return ext;
}
__device__ __forceinline__ float* out_sel(float* ext, int sel) {
    if (sel == 0) return g_act0;
    if (sel == 1) return g_act1;
    return ext;
}

// ---------------------------------------------------------------------------
// PTX helpers (baseline PTX only — harness targets plain sm_103)
// ---------------------------------------------------------------------------
__device__ __forceinline__ uint32_t smem_u32(const void* p) {
    uint32_t a;
    asm("{ .reg .u64 t; cvta.to.shared.u64 t, %1; cvt.u32.u64 %0, t; }"
        : "=r"(a) : "l"(p));
    return a;
}
#define CPASYNC16(saddr, gptr) \
    asm volatile("cp.async.cg.shared.global [%0], [%1], 16;" \
                 :: "r"(saddr), "l"(gptr) : "memory")
#define CP_COMMIT() asm volatile("cp.async.commit_group;" ::: "memory")
#define CP_WAIT1()  asm volatile("cp.async.wait_group 1;" ::: "memory")

#define LDM4(r, addr) \
    asm volatile("ldmatrix.sync.aligned.m8n8.x4.shared.b16 {%0,%1,%2,%3}, [%4];" \
                 : "=r"((r)[0]), "=r"((r)[1]), "=r"((r)[2]), "=r"((r)[3]) \
                 : "r"(addr))

#define MMA16816(d, a, b) \
    asm volatile("mma.sync.aligned.m16n8k16.row.col.f32.bf16.bf16.f32 " \
                 "{%0,%1,%2,%3}, {%4,%5,%6,%7}, {%8,%9}, {%0,%1,%2,%3};" \
                 : "+f"((d)[0]), "+f"((d)[1]), "+f"((d)[2]), "+f"((d)[3]) \
                 : "r"((a)[0]), "r"((a)[1]), "r"((a)[2]), "r"((a)[3]), \
                   "r"((b)[0]), "r"((b)[1]))

// ---------------------------------------------------------------------------
// Shared-memory layout of the MMA kernel (bytes). Pitch 72 bf16 = 144 B rows
// (conflict-free for ldmatrix: 144 % 128 = 16 -> 8 rows hit distinct banks).
// ---------------------------------------------------------------------------
#define ST_A_H   0               // A hi: 256 rows x 144 B = 36864
#define ST_A_L   36864
#define ST_B_H   73728           // B hi: 128 rows x 144 B = 18432
#define ST_B_L   92160
#define ST_BYTES 110592          // one stage
#define OFF_UF   221184          // u staging: 512 floats = 2048 B
#define SMEM_MMA 223232

// ---------------------------------------------------------------------------
// zero g_h and g_u
// ---------------------------------------------------------------------------
__global__ void zero_kernel() {
    int i = blockIdx.x * 256 + threadIdx.x;   // 131072 float4 per array
    reinterpret_cast<float4*>(g_h)[i] = make_float4(0.f, 0.f, 0.f, 0.f);
    reinterpret_cast<float4*>(g_u)[i] = make_float4(0.f, 0.f, 0.f, 0.f);
}

// ---------------------------------------------------------------------------
// g_Vx[o][0:64] = V[o][:],  g_Vx[o][64+r] = sum_s bm[r*64+s] * V[o][s]
// ---------------------------------------------------------------------------
__global__ __launch_bounds__(128)
void w2v_kernel(const float* __restrict__ V, const float* __restrict__ bm) {
    __shared__ float Vrow[64];
    __shared__ float bms[4096];
    const int o = blockIdx.x, t = threadIdx.x;
    for (int j = t; j < 4096; j += 128) bms[j] = bm[j];
    if (t < 64) Vrow[t] = V[o * 64 + t];
    __syncthreads();
    if (t < 64) {
        g_Vx[o * 128 + t] = Vrow[t];
    } else {
        const int r = t - 64;
        float s = 0.f;
#pragma unroll
        for (int ss = 0; ss < 64; ++ss) s = fmaf(bms[r * 64 + ss], Vrow[ss], s);
        g_Vx[o * 128 + 64 + r] = s;
    }
}

// ---------------------------------------------------------------------------
// Conversion: fp32 -> bf16 hi/lo planes (once per layer, elementwise).
// grid.x * 256 threads, each handles 4 elements.
// ---------------------------------------------------------------------------
__global__ __launch_bounds__(256)
void conv_kernel(const float* __restrict__ Sext, int sel, int is_b) {
    const float* S = in_sel(Sext, sel);
    __nv_bfloat16* H = is_b ? g_Bh : g_Ah;
    __nv_bfloat16* L = is_b ? g_Bl : g_Al;
    size_t i4 = (size_t)blockIdx.x * 256 + threadIdx.x;
    float4 v = reinterpret_cast<const float4*>(S)[i4];
    __nv_bfloat16 h0 = __float2bfloat16_rn(v.x), h1 = __float2bfloat16_rn(v.y);
    __nv_bfloat16 h2 = __float2bfloat16_rn(v.z), h3 = __float2bfloat16_rn(v.w);
    __nv_bfloat162 lo01 = __floats2bfloat162_rn(v.x - __bfloat162float(h0),
                                                v.y - __bfloat162float(h1));
    __nv_bfloat162 lo23 = __floats2bfloat162_rn(v.z - __bfloat162float(h2),
                                                v.w - __bfloat162float(h3));
    uint2 hp, lp;
    hp.x = (uint32_t)__bfloat16_as_ushort(h0) | ((uint32_t)__bfloat16_as_ushort(h1) << 16);
    hp.y = (uint32_t)__bfloat16_as_ushort(h2) | ((uint32_t)__bfloat16_as_ushort(h3) << 16);
    lp.x = *reinterpret_cast<uint32_t*>(&lo01);
    lp.y = *reinterpret_cast<uint32_t*>(&lo23);
    *reinterpret_cast<uint2*>(H + 4 * i4) = hp;
    *reinterpret_cast<uint2*>(L + 4 * i4) = lp;
}

// ---------------------------------------------------------------------------
// u = X @ U^T (exact fp32), k-partitioned 4 ways with atomic reduce.
// grid (128 m-tiles of 64 rows, 4 k-slices of 256), 256 threads.
// ---------------------------------------------------------------------------
__global__ __launch_bounds__(256, 2)
void u_kernel(const float* __restrict__ Xext, int xsel, const float* __restrict__ U) {
    const float* X = in_sel(Xext, xsel);
    __shared__ float sb[4352];
    const int tid = threadIdx.x;
    const int m0 = blockIdx.x * 64;
    const int kb = blockIdx.y * 256;
    const int tx = tid & 15, ty = tid >> 4;

    float acc[4][4] = {};
    for (int k0 = kb; k0 < kb + 256; k0 += 32) {
#pragma unroll
        for (int it = 0; it < 2; ++it) {
            int t = tid + it * 256;
            int row = t >> 3, quad = t & 7;
            float4 v = *reinterpret_cast<const float4*>(
                X + (size_t)(m0 + row) * Din + k0 + quad * 4);
            sb[(quad * 4 + 0) * 68 + row] = v.x;
            sb[(quad * 4 + 1) * 68 + row] = v.y;
            sb[(quad * 4 + 2) * 68 + row] = v.z;
            sb[(quad * 4 + 3) * 68 + row] = v.w;
            float4 w = *reinterpret_cast<const float4*>(
                U + (size_t)row * Din + k0 + quad * 4);
            sb[2176 + (quad * 4 + 0) * 68 + row] = w.x;
            sb[2176 + (quad * 4 + 1) * 68 + row] = w.y;
            sb[2176 + (quad * 4 + 2) * 68 + row] = w.z;
            sb[2176 + (quad * 4 + 3) * 68 + row] = w.w;
        }
        __syncthreads();
#pragma unroll
        for (int k = 0; k < 32; ++k) {
            float a[4], b[4];
#pragma unroll
            for (int i = 0; i < 4; ++i) a[i] = sb[k * 68 + ty * 4 + i];
#pragma unroll
            for (int j = 0; j < 4; ++j) b[j] = sb[2176 + k * 68 + tx * 4 + j];
#pragma unroll
            for (int i = 0; i < 4; ++i)
#pragma unroll
                for (int j = 0; j < 4; ++j) acc[i][j] += a[i] * b[j];
        }
        __syncthreads();
    }
#pragma unroll
    for (int i = 0; i < 4; ++i)
#pragma unroll
        for (int j = 0; j < 4; ++j)
            atomicAdd(&g_u[(size_t)(m0 + ty * 4 + i) * Rk + tx * 4 + j], acc[i][j]);
}

// ---------------------------------------------------------------------------
// Main GEMM: C = X @ Wm^T (bf16 3-term HMMA, preconverted planes) with fused
// einsum epilogue h[m,s] += u0*C[m,s] + u1*C[m,64+s].
// CTA M=256 x N=128, 512 threads (warp grid 4x4, warp tile 64x32),
// k-chunk 64, double-buffered cp.async. grid = (32 nb, 32 mb).
// ---------------------------------------------------------------------------
__global__ __launch_bounds__(512, 1)
void apg_mma_kernel() {
    extern __shared__ __align__(16) char sm[];
    const int t = threadIdx.x, lane = t & 31, w = t >> 5;
    const int mw = w >> 2, nw = w & 3;
    const int nb = blockIdx.x, mb = blockIdx.y;
    const int m0 = mb * 256, n0 = nb * 128;
    const uint32_t smb = smem_u32(sm);

    const __nv_bfloat16* gAh = g_Ah + (size_t)m0 * Din;
    const __nv_bfloat16* gAl = g_Al + (size_t)m0 * Din;
    const __nv_bfloat16* gBh = g_Bh + (size_t)n0 * Din;
    const __nv_bfloat16* gBl = g_Bl + (size_t)n0 * Din;

    auto issue = [&](int kc, int stg) {
        uint32_t sb0 = smb + stg * ST_BYTES;
        const __nv_bfloat16* ah = gAh + kc * 64;
        const __nv_bfloat16* al = gAl + kc * 64;
        const __nv_bfloat16* bh = gBh + kc * 64;
        const __nv_bfloat16* bl = gBl + kc * 64;
#pragma unroll
        for (int i = 0; i < 4; ++i) {
            int idx = t + i * 512, row = idx >> 3, grp = idx & 7;
            CPASYNC16(sb0 + ST_A_H + row * 144 + grp * 16, ah + (size_t)row * Din + grp * 8);
            CPASYNC16(sb0 + ST_A_L + row * 144 + grp * 16, al + (size_t)row * Din + grp * 8);
        }
#pragma unroll
        for (int i = 0; i < 2; ++i) {
            int idx = t + i * 512, row = idx >> 3, grp = idx & 7;
            CPASYNC16(sb0 + ST_B_H + row * 144 + grp * 16, bh + (size_t)row * Din + grp * 8);
            CPASYNC16(sb0 + ST_B_L + row * 144 + grp * 16, bl + (size_t)row * Din + grp * 8);
        }
    };

    // u staging (overlaps with prologue load)
    issue(0, 0);
    CP_COMMIT();
    {
        float* uf = reinterpret_cast<float*>(sm + OFF_UF);
        uf[t] = g_u[(size_t)(m0 + (t >> 1)) * Rk + 2 * nb + (t & 1)];
    }

    float acc[4][4][4];
#pragma unroll
    for (int i = 0; i < 4; ++i)
#pragma unroll
        for (int j = 0; j < 4; ++j)
#pragma unroll
            for (int e = 0; e < 4; ++e) acc[i][j][e] = 0.f;

    const int arow = lane & 15, acol = (lane >> 4) * 8;
    const int brow = ((lane >> 4) << 3) + (lane & 7), bcol = ((lane >> 3) & 1) * 8;
    const uint32_t aoff = ((mw * 64 + arow) * 72 + acol) * 2;
    const uint32_t boff = ((nw * 32 + brow) * 72 + bcol) * 2;

    for (int i = 0; i < 16; ++i) {
        if (i < 15) issue(i + 1, (i + 1) & 1);
        CP_COMMIT();
        CP_WAIT1();
        __syncthreads();                       // chunk i staged

        const uint32_t base = smb + (i & 1) * ST_BYTES;
#pragma unroll
        for (int ks = 0; ks < 4; ++ks) {
            uint32_t ah[4][4], al[4][4];
#pragma unroll
            for (int mt = 0; mt < 4; ++mt) {
                uint32_t aa = base + ST_A_H + aoff + mt * (16 * 144) + ks * 32;
                LDM4(ah[mt], aa);
                LDM4(al[mt], aa + (ST_A_L - ST_A_H));
            }
#pragma unroll
            for (int p = 0; p < 2; ++p) {
                uint32_t bb = base + ST_B_H + boff + p * (16 * 144) + ks * 32;
                uint32_t bh4[4], bl4[4];
                LDM4(bh4, bb);
                LDM4(bl4, bb + (ST_B_L - ST_B_H));
                uint32_t b0h[2] = {bh4[0], bh4[1]}, b1h[2] = {bh4[2], bh4[3]};
                uint32_t b0l[2] = {bl4[0], bl4[1]}, b1l[2] = {bl4[2], bl4[3]};
#pragma unroll
                for (int mt = 0; mt < 4; ++mt) {
                    MMA16816(acc[mt][2 * p], ah[mt], b0h);
                    MMA16816(acc[mt][2 * p], ah[mt], b0l);
                    MMA16816(acc[mt][2 * p], al[mt], b0h);
                    MMA16816(acc[mt][2 * p + 1], ah[mt], b1h);
                    MMA16816(acc[mt][2 * p + 1], ah[mt], b1l);
                    MMA16816(acc[mt][2 * p + 1], al[mt], b1h);
                }
            }
        }
        __syncthreads();                       // all warps done with stage i&1
    }

    // ---- fused einsum epilogue ----
    float* hp = reinterpret_cast<float*>(sm);              // 256 x 65 floats
    const float* uf = reinterpret_cast<const float*>(sm + OFF_UF);
    const int mbase = mw * 64, scol = (nw & 1) * 32;
    if (nw < 2) {    // cols 0..63 -> r = 2nb (u0)
#pragma unroll
        for (int mt = 0; mt < 4; ++mt)
#pragma unroll
            for (int nt = 0; nt < 4; ++nt) {
                int m0r = mbase + mt * 16 + (lane >> 2);
                int s0 = scol + nt * 8 + 2 * (lane & 3);
                hp[m0r * 65 + s0]           = acc[mt][nt][0] * uf[m0r * 2];
                hp[m0r * 65 + s0 + 1]       = acc[mt][nt][1] * uf[m0r * 2];
                hp[(m0r + 8) * 65 + s0]     = acc[mt][nt][2] * uf[(m0r + 8) * 2];
                hp[(m0r + 8) * 65 + s0 + 1] = acc[mt][nt][3] * uf[(m0r + 8) * 2];
            }
    }
    __syncthreads();
    if (nw >= 2) {   // cols 64..127 -> r = 2nb+1 (u1)
#pragma unroll
        for (int mt = 0; mt < 4; ++mt)
#pragma unroll
            for (int nt = 0; nt < 4; ++nt) {
                int m0r = mbase + mt * 16 + (lane >> 2);
                int s0 = scol + nt * 8 + 2 * (lane & 3);
                hp[m0r * 65 + s0]           += acc[mt][nt][0] * uf[m0r * 2 + 1];
                hp[m0r * 65 + s0 + 1]       += acc[mt][nt][1] * uf[m0r * 2 + 1];
                hp[(m0r + 8) * 65 + s0]     += acc[mt][nt][2] * uf[(m0r + 8) * 2 + 1];
                hp[(m0r + 8) * 65 + s0 + 1] += acc[mt][nt][3] * uf[(m0r + 8) * 2 + 1];
            }
    }
    __syncthreads();

    float* dst = g_h + (size_t)m0 * Rk;
#pragma unroll 8
    for (int ii = 0; ii < 32; ++ii) {
        int idx = ii * 512 + t;               // m = idx>>6, s = idx&63
        atomicAdd(dst + idx, hp[(idx >> 6) * 65 + (idx & 63)]);
    }
}

// ---------------------------------------------------------------------------
// out = [h | u] @ [V | W2]^T + b (+ ReLU). K=128. grid (8, 64), 256 thr.
// ---------------------------------------------------------------------------
__global__ __launch_bounds__(256, 2)
void apg_out_kernel(const float* __restrict__ bias,
                    float* __restrict__ Oext, int osel, int relu) {
    float* O = out_sel(Oext, osel);
    __shared__ float sb[8448];
    const int tid = threadIdx.x;
    const int m0 = blockIdx.y * 128;
    const int n0 = blockIdx.x * 128;
    const int tx = tid & 15, ty = tid >> 4;

    float acc[8][8] = {};
    for (int k0 = 0; k0 < 128; k0 += 32) {
        const float* Asrc = (k0 < 64) ? g_h : g_u;
        const int kk = k0 & 63;
#pragma unroll
        for (int it = 0; it < 4; ++it) {
            int t = tid + it * 256;
            int row = t >> 3, quad = t & 7;
            float4 v = *reinterpret_cast<const float4*>(
                Asrc + (size_t)(m0 + row) * Rk + kk + quad * 4);
            sb[(quad * 4 + 0) * 132 + row] = v.x;
            sb[(quad * 4 + 1) * 132 + row] = v.y;
            sb[(quad * 4 + 2) * 132 + row] = v.z;
            sb[(quad * 4 + 3) * 132 + row] = v.w;
            float4 wv = *reinterpret_cast<const float4*>(
                g_Vx + (size_t)(n0 + row) * 128 + k0 + quad * 4);
            sb[4224 + (quad * 4 + 0) * 132 + row] = wv.x;
            sb[4224 + (quad * 4 + 1) * 132 + row] = wv.y;
            sb[4224 + (quad * 4 + 2) * 132 + row] = wv.z;
            sb[4224 + (quad * 4 + 3) * 132 + row] = wv.w;
        }
        __syncthreads();
#pragma unroll
        for (int k = 0; k < 32; ++k) {
            float a[8], b[8];
            float4 a0 = *reinterpret_cast<const float4*>(sb + k * 132 + ty * 8);
            float4 a1 = *reinterpret_cast<const float4*>(sb + k * 132 + ty * 8 + 4);
            float4 b0 = *reinterpret_cast<const float4*>(sb + 4224 + k * 132 + tx * 8);
            float4 b1 = *reinterpret_cast<const float4*>(sb + 4224 + k * 132 + tx * 8 + 4);
            a[0] = a0.x; a[1] = a0.y; a[2] = a0.z; a[3] = a0.w;
            a[4] = a1.x; a[5] = a1.y; a[6] = a1.z; a[7] = a1.w;
            b[0] = b0.x; b[1] = b0.y; b[2] = b0.z; b[3] = b0.w;
            b[4] = b1.x; b[5] = b1.y; b[6] = b1.z; b[7] = b1.w;
#pragma unroll
            for (int i = 0; i < 8; ++i)
#pragma unroll
                for (int j = 0; j < 8; ++j) acc[i][j] += a[i] * b[j];
        }
        __syncthreads();
    }

    float4 bv0 = *reinterpret_cast<const float4*>(bias + n0 + tx * 8);
    float4 bv1 = *reinterpret_cast<const float4*>(bias + n0 + tx * 8 + 4);
    float bb[8] = {bv0.x, bv0.y, bv0.z, bv0.w, bv1.x, bv1.y, bv1.z, bv1.w};
#pragma unroll
    for (int i = 0; i < 8; ++i) {
        float v[8];
#pragma unroll
        for (int j = 0; j < 8; ++j) {
            v[j] = acc[i][j] + bb[j];
            if (relu) v[j] = fmaxf(v[j], 0.0f);
        }
        float4* dst = reinterpret_cast<float4*>(
            O + (size_t)(m0 + ty * 8 + i) * Din + n0 + tx * 8);
        dst[0] = make_float4(v[0], v[1], v[2], v[3]);
        dst[1] = make_float4(v[4], v[5], v[6], v[7]);
    }
}

// ---------------------------------------------------------------------------
// Launch
// ---------------------------------------------------------------------------
static void run_layer(const float* xext, int xsel,
                      const float* Wm, const float* bm, const float* U,
                      const float* V, const float* bias,
                      float* oext, int osel, int relu) {
    zero_kernel<<<512, 256>>>();
    w2v_kernel<<<Din, 128>>>(V, bm);
    conv_kernel<<<8192, 256>>>(xext, xsel, 0);   // activations -> g_Ah/g_Al
    conv_kernel<<<4096, 256>>>(Wm, 2, 1);        // Wm -> g_Bh/g_Bl
    u_kernel<<<dim3(128, 4), 256>>>(xext, xsel, U);
    apg_mma_kernel<<<dim3(32, 32), 512, SMEM_MMA>>>();
    apg_out_kernel<<<dim3(8, 64), 256>>>(bias, oext, osel, relu);
}

extern "C" void kernel_launch(void* const* d_in, const int* in_sizes, int n_in,
                              void* d_out, int out_size) {
    cudaFuncSetAttribute(apg_mma_kernel,
                         cudaFuncAttributeMaxDynamicSharedMemorySize, SMEM_MMA);
    const float* x = (const float*)d_in[0];
    run_layer(x, 2,
              (const float*)d_in[1], (const float*)d_in[2], (const float*)d_in[3],
              (const float*)d_in[4], (const float*)d_in[5],
              nullptr, 0, 1);
    run_layer(nullptr, 0,
              (const float*)d_in[6], (const float*)d_in[7], (const float*)d_in[8],
              (const float*)d_in[9], (const float*)d_in[10],
              nullptr, 1, 1);
    run_layer(nullptr, 1,
              (const float*)d_in[11], (const float*)d_in[12], (const float*)d_in[13],
              (const float*)d_in[14], (const float*)d_in[15],
              (float*)d_out, 2, 0);
}